// round 15
// baseline (speedup 1.0000x reference)
#include <cuda_runtime.h>
#include <cstdint>

#define NPT   4096
#define BATCH 4
#define KNN   20
#define NEG   0.2f
#define BNEPS 1e-5f
#define MAXC  256

#define BT    128                 // dist gemm tile (BM=BN=128)
#define NTIL  (NPT / BT)          // 32 tiles per dim
#define NTRI  (NTIL * (NTIL + 1) / 2)   // 528 upper-tri block pairs
#define BK    16                  // dist gemm k-tile
#define ARS   268                 // dup-A row stride (floats): 16B-aligned, 2-way STS max
#define TQCAP 256                 // per-row candidate buffer

// ---------------- scratch (device globals; no runtime allocation) ----------
__device__ float g_D[(size_t)BATCH * NPT * NPT];       // 256 MiB distance matrix
__device__ float g_feat[(size_t)BATCH * NPT * MAXC];   // layer activations
__device__ float g_Pp[(size_t)BATCH * NPT * MAXC];     // s * (W1 . x_j)
__device__ float g_Qq[(size_t)BATCH * NPT * MAXC];     // s * ((W2-W1) . x_n) + t
__device__ float g_sq[BATCH * NPT];
__device__ int   g_idx[BATCH * NPT * KNN];

// packed f32x2 helpers (FFMA2: 2x fp32 throughput on sm_103a)
__device__ __forceinline__ void ffma2(unsigned long long& d, unsigned long long a, unsigned long long b) {
    asm("fma.rn.f32x2 %0, %1, %2, %0;" : "+l"(d) : "l"(a), "l"(b));
}
__device__ __forceinline__ void unpack2(unsigned long long v, float& lo, float& hi) {
    unsigned r0, r1;
    asm("mov.b64 {%0, %1}, %2;" : "=r"(r0), "=r"(r1) : "l"(v));
    lo = __uint_as_float(r0); hi = __uint_as_float(r1);
}

__device__ __forceinline__ bool better(float va, int ia, float vb, int ib) {
    return (va > vb) || (va == vb && ia < ib);
}

// monotone float<->uint key (larger float => larger key)
__device__ __forceinline__ unsigned f2k(float v) {
    unsigned b = __float_as_uint(v);
    return (b & 0x80000000u) ? ~b : (b | 0x80000000u);
}
__device__ __forceinline__ float k2f(unsigned u) {
    unsigned b = (u & 0x80000000u) ? (u ^ 0x80000000u) : ~u;
    return __uint_as_float(b);
}

// ---------------- squared norms: one warp per point (with offset) -----------
__global__ void sqnorm_kernel(const float* __restrict__ feat, int C, int gw0) {
    const float* f = feat ? feat : g_feat;
    int gw   = gw0 + ((blockIdx.x * blockDim.x + threadIdx.x) >> 5);
    int lane = threadIdx.x & 31;
    if (gw >= BATCH * NPT) return;
    const float* r = f + (size_t)gw * C;
    float s = 0.f;
    for (int c = lane; c < C; c += 32) { float v = r[c]; s += v * v; }
    #pragma unroll
    for (int o = 16; o; o >>= 1) s += __shfl_down_sync(0xffffffffu, s, o);
    if (!lane) g_sq[gw] = s;
}

// ---------------- distance GEMM (symmetric, dup-A smem, pure FFMA2) ---------
// A stored twice in smem so LDS.128 yields (a,a) operand pairs directly:
// inner loop = 32 FFMA2 + 6 LDS.128, zero MOVs. launch_bounds(256,1) lifts
// the 128-reg ceiling that forced spills in the earlier dup-A attempt.
__global__ __launch_bounds__(256, 1) void dist_gemm(const float* __restrict__ feat, int C) {
    const float* f = feat ? feat : g_feat;
    int b = blockIdx.z;
    const float* A   = f    + (size_t)b * NPT * C;
    float*       Db  = g_D  + (size_t)b * NPT * NPT;
    const float* sqb = g_sq + b * NPT;

    int p = blockIdx.x;
    int bi = 0;
    #pragma unroll 1
    while (p >= NTIL - bi) { p -= NTIL - bi; bi++; }
    int bj = bi + p;
    int i0 = bi * BT, j0 = bj * BT;

    __shared__ __align__(16) float Asd[2][BK][ARS];   // duplicated A: [k][2i],[2i+1]
    __shared__ __align__(16) float Bs [2][BK][132];

    int tid = threadIdx.x;
    int tx = tid & 15, ty = tid >> 4;
    int ti = ty * 8, tj = tx * 8;
    int sk = tid & (BK - 1), si = tid >> 4;            // staging coords

    unsigned long long acc[8][4];
    #pragma unroll
    for (int i = 0; i < 8; i++)
        #pragma unroll
        for (int j = 0; j < 4; j++) acc[i][j] = 0ull;

    int nk = (C + BK - 1) / BK;

    // prologue: stage k-tile 0
    #pragma unroll
    for (int q = 0; q < 8; q++) {
        int i = si + q * 16;
        float va = (sk < C) ? A[(size_t)(i0 + i) * C + sk] : 0.f;
        float vb = (sk < C) ? A[(size_t)(j0 + i) * C + sk] : 0.f;
        Asd[0][sk][2 * i]     = va;
        Asd[0][sk][2 * i + 1] = va;
        Bs [0][sk][i]         = vb;
    }
    __syncthreads();

    #pragma unroll 1
    for (int kt = 0; kt < nk; kt++) {
        int cur = kt & 1;
        float ra[8], rb[8];
        bool more = (kt + 1) < nk;
        if (more) {
            int k0 = (kt + 1) * BK + sk;
            #pragma unroll
            for (int q = 0; q < 8; q++) {
                int i = si + q * 16;
                ra[q] = (k0 < C) ? A[(size_t)(i0 + i) * C + k0] : 0.f;
                rb[q] = (k0 < C) ? A[(size_t)(j0 + i) * C + k0] : 0.f;
            }
        }

        #pragma unroll
        for (int kk = 0; kk < BK; kk++) {
            ulonglong2 b01 = *(const ulonglong2*)&Bs[cur][kk][tj];      // (b0,b1)(b2,b3)
            ulonglong2 b23 = *(const ulonglong2*)&Bs[cur][kk][tj + 4];  // (b4,b5)(b6,b7)
            ulonglong2 a01 = *(const ulonglong2*)&Asd[cur][kk][2 * ti];       // (a0,a0)(a1,a1)
            ulonglong2 a23 = *(const ulonglong2*)&Asd[cur][kk][2 * ti + 4];
            ulonglong2 a45 = *(const ulonglong2*)&Asd[cur][kk][2 * ti + 8];
            ulonglong2 a67 = *(const ulonglong2*)&Asd[cur][kk][2 * ti + 12];
            unsigned long long av[8] = {a01.x, a01.y, a23.x, a23.y,
                                        a45.x, a45.y, a67.x, a67.y};
            #pragma unroll
            for (int i = 0; i < 8; i++) {
                ffma2(acc[i][0], av[i], b01.x);
                ffma2(acc[i][1], av[i], b01.y);
                ffma2(acc[i][2], av[i], b23.x);
                ffma2(acc[i][3], av[i], b23.y);
            }
        }

        if (more) {
            int nxt = cur ^ 1;
            #pragma unroll
            for (int q = 0; q < 8; q++) {
                int i = si + q * 16;
                Asd[nxt][sk][2 * i]     = ra[q];
                Asd[nxt][sk][2 * i + 1] = ra[q];
                Bs [nxt][sk][i]         = rb[q];
            }
        }
        __syncthreads();
    }

    int gi0 = i0 + ti, gj0 = j0 + tj;
    float si8[8], sj8[8], vals[8][8];
    #pragma unroll
    for (int i = 0; i < 8; i++) si8[i] = sqb[gi0 + i];
    #pragma unroll
    for (int j = 0; j < 8; j++) sj8[j] = sqb[gj0 + j];
    #pragma unroll
    for (int i = 0; i < 8; i++)
        #pragma unroll
        for (int jp = 0; jp < 4; jp++) {
            float lo, hi;
            unpack2(acc[i][jp], lo, hi);
            vals[i][2 * jp]     = 2.f * lo - si8[i] - sj8[2 * jp];
            vals[i][2 * jp + 1] = 2.f * hi - si8[i] - sj8[2 * jp + 1];
        }

    #pragma unroll
    for (int i = 0; i < 8; i++) {
        float4 o0 = {vals[i][0], vals[i][1], vals[i][2], vals[i][3]};
        float4 o1 = {vals[i][4], vals[i][5], vals[i][6], vals[i][7]};
        *(float4*)&Db[(size_t)(gi0 + i) * NPT + gj0]     = o0;
        *(float4*)&Db[(size_t)(gi0 + i) * NPT + gj0 + 4] = o1;
    }
    if (bi != bj) {
        #pragma unroll
        for (int j = 0; j < 8; j++) {
            float4 o0 = {vals[0][j], vals[1][j], vals[2][j], vals[3][j]};
            float4 o1 = {vals[4][j], vals[5][j], vals[6][j], vals[7][j]};
            *(float4*)&Db[(size_t)(gj0 + j) * NPT + gi0]     = o0;
            *(float4*)&Db[(size_t)(gj0 + j) * NPT + gi0 + 4] = o1;
        }
    }
}

// ---------------- warp radix select (REDUX + bit-skipping) ------------------
__device__ __forceinline__ void warp_select20(float* bv, int* bi, int n, int lane,
                                              float& tv) {
    unsigned uk[8]; int ci[8];
    unsigned kand = 0xFFFFFFFFu, kor = 0u;
    #pragma unroll
    for (int t = 0; t < 8; t++) {
        int p = lane + 32 * t;
        bool in = p < n;
        uk[t] = in ? f2k(bv[p]) : 0u;
        ci[t] = in ? bi[p] : 0x7fffffff;
        kand &= in ? uk[t] : 0xFFFFFFFFu;
        kor  |= uk[t];
    }
    __syncwarp();
    kand = __reduce_and_sync(0xffffffffu, kand);
    kor  = __reduce_or_sync(0xffffffffu, kor);
    unsigned diff = kand ^ kor;

    unsigned T = 0u;
    #pragma unroll 1
    for (int bit = 31; bit >= 0; bit--) {
        unsigned m = 1u << bit;
        if (!(diff & m)) { T |= (kand & m); continue; }   // warp-uniform skip
        unsigned Tt = T | m;
        int c = 0;
        #pragma unroll
        for (int t = 0; t < 8; t++) c += (uk[t] >= Tt) ? 1 : 0;
        c = __reduce_add_sync(0xffffffffu, c);
        if (c >= KNN) T = Tt;
    }

    int gcnt = 0;
    #pragma unroll
    for (int t = 0; t < 8; t++) gcnt += (uk[t] > T) ? 1 : 0;
    int gtot = __reduce_add_sync(0xffffffffu, gcnt);
    int ex = gcnt;
    #pragma unroll
    for (int o = 1; o < 32; o <<= 1) {
        int v = __shfl_up_sync(0xffffffffu, ex, o);
        if (lane >= o) ex += v;
    }
    ex -= gcnt;

    int w = ex;
    #pragma unroll
    for (int t = 0; t < 8; t++) {
        if (uk[t] > T) { bv[w] = k2f(uk[t]); bi[w] = ci[t]; w++; }
    }

    int need = KNN - gtot;
    int pos = gtot;
    float tvv = k2f(T);
    #pragma unroll 1
    while (need > 0) {
        int mi = 0x7fffffff;
        #pragma unroll
        for (int t = 0; t < 8; t++) if (uk[t] == T && ci[t] < mi) mi = ci[t];
        mi = __reduce_min_sync(0xffffffffu, mi);
        if (lane == 0) { bv[pos] = tvv; bi[pos] = mi; }
        #pragma unroll
        for (int t = 0; t < 8; t++) if (uk[t] == T && ci[t] == mi) uk[t] = 0u;
        pos++; need--;
    }
    __syncwarp();
    tv = tvv;
}

// ---------------- cheap conservative compaction (REDUX min) -----------------
__device__ __forceinline__ int cheap_compact(float* bv, int* bi, int cnt,
                                             int lane, float& thr) {
    float cv[8]; int ci[8]; bool vin[8];
    float lm = -3.4e38f;
    #pragma unroll
    for (int t = 0; t < 8; t++) {
        int p = lane + 32 * t;
        vin[t] = p < cnt;
        cv[t] = vin[t] ? bv[p] : -3.4e38f;
        ci[t] = vin[t] ? bi[p] : 0;
        lm = fmaxf(lm, cv[t]);
    }
    lm = k2f(__reduce_min_sync(0xffffffffu, f2k(lm)));
    __syncwarp();

    int base = 0;
    #pragma unroll
    for (int t = 0; t < 8; t++) {
        bool keep = vin[t] && (cv[t] >= lm);
        unsigned bal = __ballot_sync(0xffffffffu, keep);
        if (keep) {
            int pos = base + __popc(bal & ((1u << lane) - 1u));
            bv[pos] = cv[t]; bi[pos] = ci[t];
        }
        base += __popc(bal);
    }
    __syncwarp();
    thr = lm;
    return base;
}

// ---------------- top-20 per row: streaming filter, REDUX select ------------
__global__ __launch_bounds__(256) void topk_kernel() {
    int tid = threadIdx.x, lane = tid & 31, w = tid >> 5;
    int row = blockIdx.x * 8 + w;
    const float4* r4 = (const float4*)(g_D + (size_t)row * NPT);

    __shared__ float sbv[8][TQCAP];
    __shared__ int   sbi[8][TQCAP];
    float* bv = sbv[w]; int* bi = sbi[w];

    float thr; int thri = 0x7fffffff;
    int cnt;

    // tiles 0-1: everything passes — positional append, zero ballots
    {
        float4 d0 = r4[lane], d1 = r4[lane + 32];
        int p0 = lane * 4, p1 = 128 + lane * 4;
        bv[p0] = d0.x; bv[p0 + 1] = d0.y; bv[p0 + 2] = d0.z; bv[p0 + 3] = d0.w;
        bi[p0] = lane * 4;     bi[p0 + 1] = lane * 4 + 1;
        bi[p0 + 2] = lane * 4 + 2; bi[p0 + 3] = lane * 4 + 3;
        int b1 = (lane + 32) * 4;
        bv[p1] = d1.x; bv[p1 + 1] = d1.y; bv[p1 + 2] = d1.z; bv[p1 + 3] = d1.w;
        bi[p1] = b1; bi[p1 + 1] = b1 + 1; bi[p1 + 2] = b1 + 2; bi[p1 + 3] = b1 + 3;
        __syncwarp();
        cnt = cheap_compact(bv, bi, 256, lane, thr);
        if (cnt > 128) { warp_select20(bv, bi, cnt, lane, thr); cnt = KNN; }
    }

    float4 nxt = r4[lane + 64];
    #pragma unroll 1
    for (int t = 2; t < 32; t++) {
        float4 d = nxt;
        if (t < 31) nxt = r4[lane + 32 * (t + 1)];
        int base = (lane + 32 * t) << 2;
        float m01 = fmaxf(d.x, d.y), m23 = fmaxf(d.z, d.w);
        bool any = fmaxf(m01, m23) >= thr;
        if (__ballot_sync(0xffffffffu, any)) {
            float dv[4] = {d.x, d.y, d.z, d.w};
            #pragma unroll
            for (int c = 0; c < 4; c++) {
                bool pass = better(dv[c], base + c, thr, thri);
                unsigned bal = __ballot_sync(0xffffffffu, pass);
                if (pass) {
                    int pos = cnt + __popc(bal & ((1u << lane) - 1u));
                    bv[pos] = dv[c]; bi[pos] = base + c;
                }
                cnt += __popc(bal);
            }
            if (cnt > 128) {                       // next tile adds <=128
                cnt = cheap_compact(bv, bi, cnt, lane, thr);
                if (cnt > 128) {                   // pathological: exact fallback
                    warp_select20(bv, bi, cnt, lane, thr);
                    cnt = KNN;
                }
            }
        }
    }
    __syncwarp();
    if (cnt > KNN) warp_select20(bv, bi, cnt, lane, thr);
    if (lane < KNN) g_idx[row * KNN + lane] = bi[lane];
}

// ---------------- fused P/Q GEMM with folded BatchNorm -----------------------
__global__ __launch_bounds__(256) void pq_gemm(
    const float* __restrict__ feat, const float* __restrict__ W,
    const float* __restrict__ gg, const float* __restrict__ bb,
    const float* __restrict__ mm, const float* __restrict__ vv,
    int C, int O)
{
    const float* f = feat ? feat : g_feat;
    int i0 = blockIdx.y * 64;
    int o0 = blockIdx.x * 64;

    __shared__ __align__(16) float As[16][68];
    __shared__ __align__(16) float B1[16][68];
    __shared__ __align__(16) float B2[16][68];

    int tid = threadIdx.x;
    int tx = tid & 15, ty = tid >> 4;
    int lc = tid & 15, lr0 = tid >> 4;
    int twoC = 2 * C;

    float acc1[4][4], acc2[4][4];
    #pragma unroll
    for (int i = 0; i < 4; i++)
        #pragma unroll
        for (int j = 0; j < 4; j++) { acc1[i][j] = 0.f; acc2[i][j] = 0.f; }

    for (int k0 = 0; k0 < C; k0 += 16) {
        bool kin = (k0 + lc) < C;
        #pragma unroll
        for (int q = 0; q < 4; q++) {
            int r = lr0 + q * 16;
            As[lc][r] = kin ? f[(size_t)(i0 + r) * C + k0 + lc] : 0.f;
            B1[lc][r] = kin ? W[(size_t)(o0 + r) * twoC + k0 + lc] : 0.f;
            B2[lc][r] = kin ? W[(size_t)(o0 + r) * twoC + C + k0 + lc] : 0.f;
        }
        __syncthreads();
        #pragma unroll
        for (int kk = 0; kk < 16; kk++) {
            float4 a4  = *(const float4*)&As[kk][ty * 4];
            float4 b14 = *(const float4*)&B1[kk][tx * 4];
            float4 b24 = *(const float4*)&B2[kk][tx * 4];
            float av[4]  = {a4.x, a4.y, a4.z, a4.w};
            float b1v[4] = {b14.x, b14.y, b14.z, b14.w};
            float b2v[4] = {b24.x, b24.y, b24.z, b24.w};
            #pragma unroll
            for (int i = 0; i < 4; i++)
                #pragma unroll
                for (int j = 0; j < 4; j++) {
                    acc1[i][j] += av[i] * b1v[j];
                    acc2[i][j] += av[i] * b2v[j];
                }
        }
        __syncthreads();
    }

    #pragma unroll
    for (int j = 0; j < 4; j++) {
        int o = o0 + tx * 4 + j;
        float s = gg[o] * rsqrtf(vv[o] + BNEPS);
        float t = bb[o] - s * mm[o];
        #pragma unroll
        for (int i = 0; i < 4; i++) {
            int gi = i0 + ty * 4 + i;
            g_Pp[(size_t)gi * O + o] = s * acc1[i][j];
            g_Qq[(size_t)gi * O + o] = s * (acc2[i][j] - acc1[i][j]) + t;
        }
    }
}

// ---------------- gather neighbors + max + leaky relu ------------------------
__global__ __launch_bounds__(128) void gmax_kernel(int O, float* __restrict__ outp) {
    float* out = outp ? outp : g_feat;
    int bn = blockIdx.x;
    int b  = bn / NPT;
    __shared__ int sidx[KNN];
    if (threadIdx.x < KNN) sidx[threadIdx.x] = g_idx[bn * KNN + threadIdx.x];
    __syncthreads();
    size_t base = (size_t)b * NPT;
    for (int o = threadIdx.x; o < O; o += blockDim.x) {
        float q = g_Qq[(size_t)bn * O + o];
        float m = -3.4e38f;
        #pragma unroll
        for (int k = 0; k < KNN; k++) {
            float v = g_Pp[(base + sidx[k]) * O + o] + q;
            m = fmaxf(m, v);
        }
        out[(size_t)bn * O + o] = (m >= 0.f) ? m : NEG * m;
    }
}

// ---------------- host orchestration ----------------------------------------
// Per-layer launch order: sq, sq, dist, topk, pq, gmax — capture slot (#3)
// stays on topk_kernel (layer 1) as a no-regression check; dist change is
// attributed via the total-duration delta.
extern "C" void kernel_launch(void* const* d_in, const int* in_sizes, int n_in,
                              void* d_out, int out_size)
{
    (void)in_sizes; (void)n_in; (void)out_size;
    const float* x = (const float*)d_in[0];
    static const int dims[5] = {3, 64, 64, 128, 256};

    const float* fin = x;
    for (int l = 0; l < 4; l++) {
        int C = dims[l], O = dims[l + 1];
        const float* Wl = (const float*)d_in[1 + l * 5];
        const float* gl = (const float*)d_in[2 + l * 5];
        const float* bl = (const float*)d_in[3 + l * 5];
        const float* ml = (const float*)d_in[4 + l * 5];
        const float* vl = (const float*)d_in[5 + l * 5];

        sqnorm_kernel<<<(BATCH * NPT) / 16, 256>>>(fin, C, 0);
        sqnorm_kernel<<<(BATCH * NPT) / 16, 256>>>(fin, C, (BATCH * NPT) / 2);
        dist_gemm<<<dim3(NTRI, 1, BATCH), 256>>>(fin, C);
        topk_kernel<<<(BATCH * NPT) / 8, 256>>>();
        pq_gemm<<<dim3(O / 64, (BATCH * NPT) / 64), 256>>>(fin, Wl, gl, bl, ml, vl, C, O);
        gmax_kernel<<<BATCH * NPT, 128>>>(O, (l == 3) ? (float*)d_out : nullptr);

        fin = nullptr;
    }
}

// round 16
// speedup vs baseline: 1.0514x; 1.0514x over previous
#include <cuda_runtime.h>
#include <cstdint>

#define NPT   4096
#define BATCH 4
#define KNN   20
#define NEG   0.2f
#define BNEPS 1e-5f
#define MAXC  256

#define BT    128                 // dist gemm tile (BM=BN=128)
#define NTIL  (NPT / BT)          // 32 tiles per dim
#define NTRI  (NTIL * (NTIL + 1) / 2)   // 528 upper-tri block pairs
#define BK    16                  // dist gemm k-tile
#define TQCAP 256                 // per-row candidate buffer

// ---------------- scratch (device globals; no runtime allocation) ----------
__device__ float g_D[(size_t)BATCH * NPT * NPT];       // 256 MiB distance matrix
__device__ float g_feat[(size_t)BATCH * NPT * MAXC];   // layer activations
__device__ float g_Pp[(size_t)BATCH * NPT * MAXC];     // s * (W1 . x_j)
__device__ float g_Qq[(size_t)BATCH * NPT * MAXC];     // s * ((W2-W1) . x_n) + t
__device__ float g_sq[BATCH * NPT];
__device__ int   g_idx[BATCH * NPT * KNN];

// packed f32x2 helpers (FFMA2: 2x fp32 throughput on sm_103a)
__device__ __forceinline__ unsigned long long pack2(float lo, float hi) {
    unsigned long long r;
    asm("mov.b64 %0, {%1, %2};" : "=l"(r) : "r"(__float_as_uint(lo)), "r"(__float_as_uint(hi)));
    return r;
}
__device__ __forceinline__ unsigned long long dup2(float v) {
    unsigned long long r;
    asm("mov.b64 %0, {%1, %1};" : "=l"(r) : "r"(__float_as_uint(v)));
    return r;
}
__device__ __forceinline__ void ffma2(unsigned long long& d, unsigned long long a, unsigned long long b) {
    asm("fma.rn.f32x2 %0, %1, %2, %0;" : "+l"(d) : "l"(a), "l"(b));
}
__device__ __forceinline__ void unpack2(unsigned long long v, float& lo, float& hi) {
    unsigned r0, r1;
    asm("mov.b64 {%0, %1}, %2;" : "=r"(r0), "=r"(r1) : "l"(v));
    lo = __uint_as_float(r0); hi = __uint_as_float(r1);
}

__device__ __forceinline__ bool better(float va, int ia, float vb, int ib) {
    return (va > vb) || (va == vb && ia < ib);
}

// monotone float<->uint key (larger float => larger key)
__device__ __forceinline__ unsigned f2k(float v) {
    unsigned b = __float_as_uint(v);
    return (b & 0x80000000u) ? ~b : (b | 0x80000000u);
}
__device__ __forceinline__ float k2f(unsigned u) {
    unsigned b = (u & 0x80000000u) ? (u ^ 0x80000000u) : ~u;
    return __uint_as_float(b);
}

// ---------------- squared norms: one warp per point (with offset) -----------
__global__ void sqnorm_kernel(const float* __restrict__ feat, int C, int gw0) {
    const float* f = feat ? feat : g_feat;
    int gw   = gw0 + ((blockIdx.x * blockDim.x + threadIdx.x) >> 5);
    int lane = threadIdx.x & 31;
    if (gw >= BATCH * NPT) return;
    const float* r = f + (size_t)gw * C;
    float s = 0.f;
    for (int c = lane; c < C; c += 32) { float v = r[c]; s += v * v; }
    #pragma unroll
    for (int o = 16; o; o >>= 1) s += __shfl_down_sync(0xffffffffu, s, o);
    if (!lane) g_sq[gw] = s;
}

// ---------------- distance GEMM (round-11 version, single batch) ------------
__global__ __launch_bounds__(256) void dist_gemm(const float* __restrict__ feat, int C, int b) {
    const float* f = feat ? feat : g_feat;
    const float* A   = f    + (size_t)b * NPT * C;
    float*       Db  = g_D  + (size_t)b * NPT * NPT;
    const float* sqb = g_sq + b * NPT;

    int p = blockIdx.x;
    int bi = 0;
    #pragma unroll 1
    while (p >= NTIL - bi) { p -= NTIL - bi; bi++; }
    int bj = bi + p;
    int i0 = bi * BT, j0 = bj * BT;

    __shared__ __align__(16) float As[2][BK][132];
    __shared__ __align__(16) float Bs[2][BK][132];

    int tid = threadIdx.x;
    int tx = tid & 15, ty = tid >> 4;
    int ti = ty * 8, tj = tx * 8;

    unsigned long long acc[8][4];
    #pragma unroll
    for (int i = 0; i < 8; i++)
        #pragma unroll
        for (int j = 0; j < 4; j++) acc[i][j] = 0ull;

    int nk = (C + BK - 1) / BK;

    #pragma unroll
    for (int q = 0; q < 8; q++) {
        int lin = tid + q * 256;
        int k = lin & (BK - 1), i = lin >> 4;
        As[0][k][i] = (k < C) ? A[(size_t)(i0 + i) * C + k] : 0.f;
        Bs[0][k][i] = (k < C) ? A[(size_t)(j0 + i) * C + k] : 0.f;
    }
    __syncthreads();

    #pragma unroll 1
    for (int kt = 0; kt < nk; kt++) {
        int cur = kt & 1;
        float ra[8], rb[8];
        bool more = (kt + 1) < nk;
        if (more) {
            int k0 = (kt + 1) * BK;
            #pragma unroll
            for (int q = 0; q < 8; q++) {
                int lin = tid + q * 256;
                int k = k0 + (lin & (BK - 1)), i = lin >> 4;
                ra[q] = (k < C) ? A[(size_t)(i0 + i) * C + k] : 0.f;
                rb[q] = (k < C) ? A[(size_t)(j0 + i) * C + k] : 0.f;
            }
        }

        #pragma unroll
        for (int kk = 0; kk < BK; kk++) {
            float4 a0 = *(const float4*)&As[cur][kk][ti];
            float4 a1 = *(const float4*)&As[cur][kk][ti + 4];
            float4 b0 = *(const float4*)&Bs[cur][kk][tj];
            float4 b1 = *(const float4*)&Bs[cur][kk][tj + 4];
            unsigned long long bp[4];
            bp[0] = pack2(b0.x, b0.y); bp[1] = pack2(b0.z, b0.w);
            bp[2] = pack2(b1.x, b1.y); bp[3] = pack2(b1.z, b1.w);
            float av[8] = {a0.x, a0.y, a0.z, a0.w, a1.x, a1.y, a1.z, a1.w};
            #pragma unroll
            for (int i = 0; i < 8; i++) {
                unsigned long long ad = dup2(av[i]);
                ffma2(acc[i][0], ad, bp[0]);
                ffma2(acc[i][1], ad, bp[1]);
                ffma2(acc[i][2], ad, bp[2]);
                ffma2(acc[i][3], ad, bp[3]);
            }
        }

        if (more) {
            int nxt = cur ^ 1;
            #pragma unroll
            for (int q = 0; q < 8; q++) {
                int lin = tid + q * 256;
                int k = lin & (BK - 1), i = lin >> 4;
                As[nxt][k][i] = ra[q];
                Bs[nxt][k][i] = rb[q];
            }
        }
        __syncthreads();
    }

    int gi0 = i0 + ti, gj0 = j0 + tj;
    float si[8], sj[8], vals[8][8];
    #pragma unroll
    for (int i = 0; i < 8; i++) si[i] = sqb[gi0 + i];
    #pragma unroll
    for (int j = 0; j < 8; j++) sj[j] = sqb[gj0 + j];
    #pragma unroll
    for (int i = 0; i < 8; i++)
        #pragma unroll
        for (int jp = 0; jp < 4; jp++) {
            float lo, hi;
            unpack2(acc[i][jp], lo, hi);
            vals[i][2 * jp]     = 2.f * lo - si[i] - sj[2 * jp];
            vals[i][2 * jp + 1] = 2.f * hi - si[i] - sj[2 * jp + 1];
        }

    #pragma unroll
    for (int i = 0; i < 8; i++) {
        float4 o0 = {vals[i][0], vals[i][1], vals[i][2], vals[i][3]};
        float4 o1 = {vals[i][4], vals[i][5], vals[i][6], vals[i][7]};
        *(float4*)&Db[(size_t)(gi0 + i) * NPT + gj0]     = o0;
        *(float4*)&Db[(size_t)(gi0 + i) * NPT + gj0 + 4] = o1;
    }
    if (bi != bj) {
        #pragma unroll
        for (int j = 0; j < 8; j++) {
            float4 o0 = {vals[0][j], vals[1][j], vals[2][j], vals[3][j]};
            float4 o1 = {vals[4][j], vals[5][j], vals[6][j], vals[7][j]};
            *(float4*)&Db[(size_t)(gj0 + j) * NPT + gi0]     = o0;
            *(float4*)&Db[(size_t)(gj0 + j) * NPT + gi0 + 4] = o1;
        }
    }
}

// ---------------- warp radix select (REDUX + bit-skipping) ------------------
__device__ __forceinline__ void warp_select20(float* bv, int* bi, int n, int lane,
                                              float& tv) {
    unsigned uk[8]; int ci[8];
    unsigned kand = 0xFFFFFFFFu, kor = 0u;
    #pragma unroll
    for (int t = 0; t < 8; t++) {
        int p = lane + 32 * t;
        bool in = p < n;
        uk[t] = in ? f2k(bv[p]) : 0u;
        ci[t] = in ? bi[p] : 0x7fffffff;
        kand &= in ? uk[t] : 0xFFFFFFFFu;
        kor  |= uk[t];
    }
    __syncwarp();
    kand = __reduce_and_sync(0xffffffffu, kand);
    kor  = __reduce_or_sync(0xffffffffu, kor);
    unsigned diff = kand ^ kor;

    unsigned T = 0u;
    #pragma unroll 1
    for (int bit = 31; bit >= 0; bit--) {
        unsigned m = 1u << bit;
        if (!(diff & m)) { T |= (kand & m); continue; }
        unsigned Tt = T | m;
        int c = 0;
        #pragma unroll
        for (int t = 0; t < 8; t++) c += (uk[t] >= Tt) ? 1 : 0;
        c = __reduce_add_sync(0xffffffffu, c);
        if (c >= KNN) T = Tt;
    }

    int gcnt = 0;
    #pragma unroll
    for (int t = 0; t < 8; t++) gcnt += (uk[t] > T) ? 1 : 0;
    int gtot = __reduce_add_sync(0xffffffffu, gcnt);
    int ex = gcnt;
    #pragma unroll
    for (int o = 1; o < 32; o <<= 1) {
        int v = __shfl_up_sync(0xffffffffu, ex, o);
        if (lane >= o) ex += v;
    }
    ex -= gcnt;

    int w = ex;
    #pragma unroll
    for (int t = 0; t < 8; t++) {
        if (uk[t] > T) { bv[w] = k2f(uk[t]); bi[w] = ci[t]; w++; }
    }

    int need = KNN - gtot;
    int pos = gtot;
    float tvv = k2f(T);
    #pragma unroll 1
    while (need > 0) {
        int mi = 0x7fffffff;
        #pragma unroll
        for (int t = 0; t < 8; t++) if (uk[t] == T && ci[t] < mi) mi = ci[t];
        mi = __reduce_min_sync(0xffffffffu, mi);
        if (lane == 0) { bv[pos] = tvv; bi[pos] = mi; }
        #pragma unroll
        for (int t = 0; t < 8; t++) if (uk[t] == T && ci[t] == mi) uk[t] = 0u;
        pos++; need--;
    }
    __syncwarp();
    tv = tvv;
}

// ---------------- cheap conservative compaction (REDUX min) -----------------
__device__ __forceinline__ int cheap_compact(float* bv, int* bi, int cnt,
                                             int lane, float& thr) {
    float cv[8]; int ci[8]; bool vin[8];
    float lm = -3.4e38f;
    #pragma unroll
    for (int t = 0; t < 8; t++) {
        int p = lane + 32 * t;
        vin[t] = p < cnt;
        cv[t] = vin[t] ? bv[p] : -3.4e38f;
        ci[t] = vin[t] ? bi[p] : 0;
        lm = fmaxf(lm, cv[t]);
    }
    lm = k2f(__reduce_min_sync(0xffffffffu, f2k(lm)));
    __syncwarp();

    int base = 0;
    #pragma unroll
    for (int t = 0; t < 8; t++) {
        bool keep = vin[t] && (cv[t] >= lm);
        unsigned bal = __ballot_sync(0xffffffffu, keep);
        if (keep) {
            int pos = base + __popc(bal & ((1u << lane) - 1u));
            bv[pos] = cv[t]; bi[pos] = ci[t];
        }
        base += __popc(bal);
    }
    __syncwarp();
    thr = lm;
    return base;
}

// ---------------- top-20 per row (single batch): streaming filter -----------
__global__ __launch_bounds__(256) void topk_kernel(int b) {
    int tid = threadIdx.x, lane = tid & 31, w = tid >> 5;
    int row = blockIdx.x * 8 + w;                  // row within batch
    const float4* r4 = (const float4*)(g_D + ((size_t)b * NPT + row) * NPT);

    __shared__ float sbv[8][TQCAP];
    __shared__ int   sbi[8][TQCAP];
    float* bv = sbv[w]; int* bi = sbi[w];

    float thr; int thri = 0x7fffffff;
    int cnt;

    // tiles 0-1: everything passes — positional append, zero ballots
    {
        float4 d0 = r4[lane], d1 = r4[lane + 32];
        int p0 = lane * 4, p1 = 128 + lane * 4;
        bv[p0] = d0.x; bv[p0 + 1] = d0.y; bv[p0 + 2] = d0.z; bv[p0 + 3] = d0.w;
        bi[p0] = lane * 4;     bi[p0 + 1] = lane * 4 + 1;
        bi[p0 + 2] = lane * 4 + 2; bi[p0 + 3] = lane * 4 + 3;
        int b1 = (lane + 32) * 4;
        bv[p1] = d1.x; bv[p1 + 1] = d1.y; bv[p1 + 2] = d1.z; bv[p1 + 3] = d1.w;
        bi[p1] = b1; bi[p1 + 1] = b1 + 1; bi[p1 + 2] = b1 + 2; bi[p1 + 3] = b1 + 3;
        __syncwarp();
        cnt = cheap_compact(bv, bi, 256, lane, thr);
        if (cnt > 128) { warp_select20(bv, bi, cnt, lane, thr); cnt = KNN; }
    }

    float4 nxt = r4[lane + 64];
    #pragma unroll 1
    for (int t = 2; t < 32; t++) {
        float4 d = nxt;
        if (t < 31) nxt = r4[lane + 32 * (t + 1)];
        int base = (lane + 32 * t) << 2;
        float m01 = fmaxf(d.x, d.y), m23 = fmaxf(d.z, d.w);
        bool any = fmaxf(m01, m23) >= thr;
        if (__ballot_sync(0xffffffffu, any)) {
            float dv[4] = {d.x, d.y, d.z, d.w};
            #pragma unroll
            for (int c = 0; c < 4; c++) {
                bool pass = better(dv[c], base + c, thr, thri);
                unsigned bal = __ballot_sync(0xffffffffu, pass);
                if (pass) {
                    int pos = cnt + __popc(bal & ((1u << lane) - 1u));
                    bv[pos] = dv[c]; bi[pos] = base + c;
                }
                cnt += __popc(bal);
            }
            if (cnt > 128) {                       // next tile adds <=128
                cnt = cheap_compact(bv, bi, cnt, lane, thr);
                if (cnt > 128) {                   // pathological: exact fallback
                    warp_select20(bv, bi, cnt, lane, thr);
                    cnt = KNN;
                }
            }
        }
    }
    __syncwarp();
    if (cnt > KNN) warp_select20(bv, bi, cnt, lane, thr);
    if (lane < KNN) g_idx[((size_t)b * NPT + row) * KNN + lane] = bi[lane];
}

// ---------------- fused P/Q GEMM with folded BatchNorm -----------------------
__global__ __launch_bounds__(256) void pq_gemm(
    const float* __restrict__ feat, const float* __restrict__ W,
    const float* __restrict__ gg, const float* __restrict__ bb,
    const float* __restrict__ mm, const float* __restrict__ vv,
    int C, int O)
{
    const float* f = feat ? feat : g_feat;
    int i0 = blockIdx.y * 64;
    int o0 = blockIdx.x * 64;

    __shared__ __align__(16) float As[16][68];
    __shared__ __align__(16) float B1[16][68];
    __shared__ __align__(16) float B2[16][68];

    int tid = threadIdx.x;
    int tx = tid & 15, ty = tid >> 4;
    int lc = tid & 15, lr0 = tid >> 4;
    int twoC = 2 * C;

    float acc1[4][4], acc2[4][4];
    #pragma unroll
    for (int i = 0; i < 4; i++)
        #pragma unroll
        for (int j = 0; j < 4; j++) { acc1[i][j] = 0.f; acc2[i][j] = 0.f; }

    for (int k0 = 0; k0 < C; k0 += 16) {
        bool kin = (k0 + lc) < C;
        #pragma unroll
        for (int q = 0; q < 4; q++) {
            int r = lr0 + q * 16;
            As[lc][r] = kin ? f[(size_t)(i0 + r) * C + k0 + lc] : 0.f;
            B1[lc][r] = kin ? W[(size_t)(o0 + r) * twoC + k0 + lc] : 0.f;
            B2[lc][r] = kin ? W[(size_t)(o0 + r) * twoC + C + k0 + lc] : 0.f;
        }
        __syncthreads();
        #pragma unroll
        for (int kk = 0; kk < 16; kk++) {
            float4 a4  = *(const float4*)&As[kk][ty * 4];
            float4 b14 = *(const float4*)&B1[kk][tx * 4];
            float4 b24 = *(const float4*)&B2[kk][tx * 4];
            float av[4]  = {a4.x, a4.y, a4.z, a4.w};
            float b1v[4] = {b14.x, b14.y, b14.z, b14.w};
            float b2v[4] = {b24.x, b24.y, b24.z, b24.w};
            #pragma unroll
            for (int i = 0; i < 4; i++)
                #pragma unroll
                for (int j = 0; j < 4; j++) {
                    acc1[i][j] += av[i] * b1v[j];
                    acc2[i][j] += av[i] * b2v[j];
                }
        }
        __syncthreads();
    }

    #pragma unroll
    for (int j = 0; j < 4; j++) {
        int o = o0 + tx * 4 + j;
        float s = gg[o] * rsqrtf(vv[o] + BNEPS);
        float t = bb[o] - s * mm[o];
        #pragma unroll
        for (int i = 0; i < 4; i++) {
            int gi = i0 + ty * 4 + i;
            g_Pp[(size_t)gi * O + o] = s * acc1[i][j];
            g_Qq[(size_t)gi * O + o] = s * (acc2[i][j] - acc1[i][j]) + t;
        }
    }
}

// ---------------- gather neighbors + max + leaky relu ------------------------
__global__ __launch_bounds__(128) void gmax_kernel(int O, float* __restrict__ outp) {
    float* out = outp ? outp : g_feat;
    int bn = blockIdx.x;
    int b  = bn / NPT;
    __shared__ int sidx[KNN];
    if (threadIdx.x < KNN) sidx[threadIdx.x] = g_idx[bn * KNN + threadIdx.x];
    __syncthreads();
    size_t base = (size_t)b * NPT;
    for (int o = threadIdx.x; o < O; o += blockDim.x) {
        float q = g_Qq[(size_t)bn * O + o];
        float m = -3.4e38f;
        #pragma unroll
        for (int k = 0; k < KNN; k++) {
            float v = g_Pp[(base + sidx[k]) * O + o] + q;
            m = fmaxf(m, v);
        }
        out[(size_t)bn * O + o] = (m >= 0.f) ? m : NEG * m;
    }
}

// ---------------- host orchestration: fork/join overlap ----------------------
// Main stream: sq, dist(b=0..3). Side stream: pq, then topk(b) as each dist(b)
// completes (event fork). Join before gmax. dist (stall-bound, issue ~20%) and
// topk (ALU-bound, issue ~78%) use complementary pipes, so topk hides under
// dist. Stream/events are created fresh each call (host-side only; never
// destroyed mid-capture).
extern "C" void kernel_launch(void* const* d_in, const int* in_sizes, int n_in,
                              void* d_out, int out_size)
{
    (void)in_sizes; (void)n_in; (void)out_size;
    const float* x = (const float*)d_in[0];
    static const int dims[5] = {3, 64, 64, 128, 256};

    cudaStream_t s1;
    cudaStreamCreateWithFlags(&s1, cudaStreamNonBlocking);

    const float* fin = x;
    for (int l = 0; l < 4; l++) {
        int C = dims[l], O = dims[l + 1];
        const float* Wl = (const float*)d_in[1 + l * 5];
        const float* gl = (const float*)d_in[2 + l * 5];
        const float* bl = (const float*)d_in[3 + l * 5];
        const float* ml = (const float*)d_in[4 + l * 5];
        const float* vl = (const float*)d_in[5 + l * 5];

        sqnorm_kernel<<<(BATCH * NPT) / 16, 256>>>(fin, C, 0);
        sqnorm_kernel<<<(BATCH * NPT) / 16, 256>>>(fin, C, (BATCH * NPT) / 2);

        // fork side stream after sqnorm (pq depends only on fin)
        cudaEvent_t eA;
        cudaEventCreateWithFlags(&eA, cudaEventDisableTiming);
        cudaEventRecord(eA, 0);
        cudaStreamWaitEvent(s1, eA, 0);
        pq_gemm<<<dim3(O / 64, (BATCH * NPT) / 64), 256, 0, s1>>>(fin, Wl, gl, bl, ml, vl, C, O);

        for (int b = 0; b < BATCH; b++) {
            dist_gemm<<<NTRI, 256>>>(fin, C, b);
            cudaEvent_t eB;
            cudaEventCreateWithFlags(&eB, cudaEventDisableTiming);
            cudaEventRecord(eB, 0);
            cudaStreamWaitEvent(s1, eB, 0);
            topk_kernel<<<NPT / 8, 256, 0, s1>>>(b);
        }

        // join: gmax needs all topk + pq results
        cudaEvent_t eT;
        cudaEventCreateWithFlags(&eT, cudaEventDisableTiming);
        cudaEventRecord(eT, s1);
        cudaStreamWaitEvent(0, eT, 0);
        gmax_kernel<<<BATCH * NPT, 128>>>(O, (l == 3) ? (float*)d_out : nullptr);

        fin = nullptr;
    }
}

// round 17
// speedup vs baseline: 1.1720x; 1.1147x over previous
#include <cuda_runtime.h>
#include <cstdint>

#define NPT   4096
#define BATCH 4
#define KNN   20
#define NEG   0.2f
#define BNEPS 1e-5f
#define MAXC  256

#define BT    128                 // dist gemm tile (BM=BN=128)
#define NTIL  (NPT / BT)          // 32 tiles per dim
#define NTRI  (NTIL * (NTIL + 1) / 2)   // 528 upper-tri block pairs
#define BK    16                  // dist gemm k-tile
#define TQCAP 256                 // per-row candidate buffer

// ---------------- scratch (device globals; no runtime allocation) ----------
__device__ float g_D[(size_t)BATCH * NPT * NPT];       // 256 MiB distance matrix
__device__ float g_feat[(size_t)BATCH * NPT * MAXC];   // layer activations
__device__ float g_Pp[(size_t)BATCH * NPT * MAXC];     // s * (W1 . x_j)
__device__ float g_Qq[(size_t)BATCH * NPT * MAXC];     // s * ((W2-W1) . x_n) + t
__device__ float g_sq[BATCH * NPT];
__device__ int   g_idx[BATCH * NPT * KNN];

// packed f32x2 helpers (FFMA2: 2x fp32 throughput on sm_103a)
__device__ __forceinline__ unsigned long long pack2(float lo, float hi) {
    unsigned long long r;
    asm("mov.b64 %0, {%1, %2};" : "=l"(r) : "r"(__float_as_uint(lo)), "r"(__float_as_uint(hi)));
    return r;
}
__device__ __forceinline__ unsigned long long dup2(float v) {
    unsigned long long r;
    asm("mov.b64 %0, {%1, %1};" : "=l"(r) : "r"(__float_as_uint(v)));
    return r;
}
__device__ __forceinline__ void ffma2(unsigned long long& d, unsigned long long a, unsigned long long b) {
    asm("fma.rn.f32x2 %0, %1, %2, %0;" : "+l"(d) : "l"(a), "l"(b));
}
__device__ __forceinline__ void unpack2(unsigned long long v, float& lo, float& hi) {
    unsigned r0, r1;
    asm("mov.b64 {%0, %1}, %2;" : "=r"(r0), "=r"(r1) : "l"(v));
    lo = __uint_as_float(r0); hi = __uint_as_float(r1);
}

__device__ __forceinline__ bool better(float va, int ia, float vb, int ib) {
    return (va > vb) || (va == vb && ia < ib);
}

// monotone float<->uint key (larger float => larger key)
__device__ __forceinline__ unsigned f2k(float v) {
    unsigned b = __float_as_uint(v);
    return (b & 0x80000000u) ? ~b : (b | 0x80000000u);
}
__device__ __forceinline__ float k2f(unsigned u) {
    unsigned b = (u & 0x80000000u) ? (u ^ 0x80000000u) : ~u;
    return __uint_as_float(b);
}

// ---------------- squared norms: one warp per point (with offset) -----------
__global__ void sqnorm_kernel(const float* __restrict__ feat, int C, int gw0) {
    const float* f = feat ? feat : g_feat;
    int gw   = gw0 + ((blockIdx.x * blockDim.x + threadIdx.x) >> 5);
    int lane = threadIdx.x & 31;
    if (gw >= BATCH * NPT) return;
    const float* r = f + (size_t)gw * C;
    float s = 0.f;
    for (int c = lane; c < C; c += 32) { float v = r[c]; s += v * v; }
    #pragma unroll
    for (int o = 16; o; o >>= 1) s += __shfl_down_sync(0xffffffffu, s, o);
    if (!lane) g_sq[gw] = s;
}

// ---------------- distance GEMM (round-11/14 version: symmetric, f32x2) -----
__global__ __launch_bounds__(256) void dist_gemm(const float* __restrict__ feat, int C) {
    const float* f = feat ? feat : g_feat;
    int b = blockIdx.z;
    const float* A   = f    + (size_t)b * NPT * C;
    float*       Db  = g_D  + (size_t)b * NPT * NPT;
    const float* sqb = g_sq + b * NPT;

    int p = blockIdx.x;
    int bi = 0;
    #pragma unroll 1
    while (p >= NTIL - bi) { p -= NTIL - bi; bi++; }
    int bj = bi + p;
    int i0 = bi * BT, j0 = bj * BT;

    __shared__ __align__(16) float As[2][BK][132];
    __shared__ __align__(16) float Bs[2][BK][132];

    int tid = threadIdx.x;
    int tx = tid & 15, ty = tid >> 4;
    int ti = ty * 8, tj = tx * 8;

    unsigned long long acc[8][4];
    #pragma unroll
    for (int i = 0; i < 8; i++)
        #pragma unroll
        for (int j = 0; j < 4; j++) acc[i][j] = 0ull;

    int nk = (C + BK - 1) / BK;

    #pragma unroll
    for (int q = 0; q < 8; q++) {
        int lin = tid + q * 256;
        int k = lin & (BK - 1), i = lin >> 4;
        As[0][k][i] = (k < C) ? A[(size_t)(i0 + i) * C + k] : 0.f;
        Bs[0][k][i] = (k < C) ? A[(size_t)(j0 + i) * C + k] : 0.f;
    }
    __syncthreads();

    #pragma unroll 1
    for (int kt = 0; kt < nk; kt++) {
        int cur = kt & 1;
        float ra[8], rb[8];
        bool more = (kt + 1) < nk;
        if (more) {
            int k0 = (kt + 1) * BK;
            #pragma unroll
            for (int q = 0; q < 8; q++) {
                int lin = tid + q * 256;
                int k = k0 + (lin & (BK - 1)), i = lin >> 4;
                ra[q] = (k < C) ? A[(size_t)(i0 + i) * C + k] : 0.f;
                rb[q] = (k < C) ? A[(size_t)(j0 + i) * C + k] : 0.f;
            }
        }

        #pragma unroll
        for (int kk = 0; kk < BK; kk++) {
            float4 a0 = *(const float4*)&As[cur][kk][ti];
            float4 a1 = *(const float4*)&As[cur][kk][ti + 4];
            float4 b0 = *(const float4*)&Bs[cur][kk][tj];
            float4 b1 = *(const float4*)&Bs[cur][kk][tj + 4];
            unsigned long long bp[4];
            bp[0] = pack2(b0.x, b0.y); bp[1] = pack2(b0.z, b0.w);
            bp[2] = pack2(b1.x, b1.y); bp[3] = pack2(b1.z, b1.w);
            float av[8] = {a0.x, a0.y, a0.z, a0.w, a1.x, a1.y, a1.z, a1.w};
            #pragma unroll
            for (int i = 0; i < 8; i++) {
                unsigned long long ad = dup2(av[i]);
                ffma2(acc[i][0], ad, bp[0]);
                ffma2(acc[i][1], ad, bp[1]);
                ffma2(acc[i][2], ad, bp[2]);
                ffma2(acc[i][3], ad, bp[3]);
            }
        }

        if (more) {
            int nxt = cur ^ 1;
            #pragma unroll
            for (int q = 0; q < 8; q++) {
                int lin = tid + q * 256;
                int k = lin & (BK - 1), i = lin >> 4;
                As[nxt][k][i] = ra[q];
                Bs[nxt][k][i] = rb[q];
            }
        }
        __syncthreads();
    }

    int gi0 = i0 + ti, gj0 = j0 + tj;
    float si[8], sj[8], vals[8][8];
    #pragma unroll
    for (int i = 0; i < 8; i++) si[i] = sqb[gi0 + i];
    #pragma unroll
    for (int j = 0; j < 8; j++) sj[j] = sqb[gj0 + j];
    #pragma unroll
    for (int i = 0; i < 8; i++)
        #pragma unroll
        for (int jp = 0; jp < 4; jp++) {
            float lo, hi;
            unpack2(acc[i][jp], lo, hi);
            vals[i][2 * jp]     = 2.f * lo - si[i] - sj[2 * jp];
            vals[i][2 * jp + 1] = 2.f * hi - si[i] - sj[2 * jp + 1];
        }

    #pragma unroll
    for (int i = 0; i < 8; i++) {
        float4 o0 = {vals[i][0], vals[i][1], vals[i][2], vals[i][3]};
        float4 o1 = {vals[i][4], vals[i][5], vals[i][6], vals[i][7]};
        *(float4*)&Db[(size_t)(gi0 + i) * NPT + gj0]     = o0;
        *(float4*)&Db[(size_t)(gi0 + i) * NPT + gj0 + 4] = o1;
    }
    if (bi != bj) {
        #pragma unroll
        for (int j = 0; j < 8; j++) {
            float4 o0 = {vals[0][j], vals[1][j], vals[2][j], vals[3][j]};
            float4 o1 = {vals[4][j], vals[5][j], vals[6][j], vals[7][j]};
            *(float4*)&Db[(size_t)(gj0 + j) * NPT + gi0]     = o0;
            *(float4*)&Db[(size_t)(gj0 + j) * NPT + gi0 + 4] = o1;
        }
    }
}

// ---------------- warp radix select (REDUX + bit-skipping) ------------------
__device__ __forceinline__ void warp_select20(float* bv, int* bi, int n, int lane,
                                              float& tv) {
    unsigned uk[8]; int ci[8];
    unsigned kand = 0xFFFFFFFFu, kor = 0u;
    #pragma unroll
    for (int t = 0; t < 8; t++) {
        int p = lane + 32 * t;
        bool in = p < n;
        uk[t] = in ? f2k(bv[p]) : 0u;
        ci[t] = in ? bi[p] : 0x7fffffff;
        kand &= in ? uk[t] : 0xFFFFFFFFu;
        kor  |= uk[t];
    }
    __syncwarp();
    kand = __reduce_and_sync(0xffffffffu, kand);
    kor  = __reduce_or_sync(0xffffffffu, kor);
    unsigned diff = kand ^ kor;

    unsigned T = 0u;
    #pragma unroll 1
    for (int bit = 31; bit >= 0; bit--) {
        unsigned m = 1u << bit;
        if (!(diff & m)) { T |= (kand & m); continue; }   // warp-uniform skip
        unsigned Tt = T | m;
        int c = 0;
        #pragma unroll
        for (int t = 0; t < 8; t++) c += (uk[t] >= Tt) ? 1 : 0;
        c = __reduce_add_sync(0xffffffffu, c);
        if (c >= KNN) T = Tt;
    }

    int gcnt = 0;
    #pragma unroll
    for (int t = 0; t < 8; t++) gcnt += (uk[t] > T) ? 1 : 0;
    int gtot = __reduce_add_sync(0xffffffffu, gcnt);
    int ex = gcnt;
    #pragma unroll
    for (int o = 1; o < 32; o <<= 1) {
        int v = __shfl_up_sync(0xffffffffu, ex, o);
        if (lane >= o) ex += v;
    }
    ex -= gcnt;

    int w = ex;
    #pragma unroll
    for (int t = 0; t < 8; t++) {
        if (uk[t] > T) { bv[w] = k2f(uk[t]); bi[w] = ci[t]; w++; }
    }

    int need = KNN - gtot;
    int pos = gtot;
    float tvv = k2f(T);
    #pragma unroll 1
    while (need > 0) {
        int mi = 0x7fffffff;
        #pragma unroll
        for (int t = 0; t < 8; t++) if (uk[t] == T && ci[t] < mi) mi = ci[t];
        mi = __reduce_min_sync(0xffffffffu, mi);
        if (lane == 0) { bv[pos] = tvv; bi[pos] = mi; }
        #pragma unroll
        for (int t = 0; t < 8; t++) if (uk[t] == T && ci[t] == mi) uk[t] = 0u;
        pos++; need--;
    }
    __syncwarp();
    tv = tvv;
}

// ---------------- cheap conservative compaction (REDUX min) -----------------
__device__ __forceinline__ int cheap_compact(float* bv, int* bi, int cnt,
                                             int lane, float& thr) {
    float cv[8]; int ci[8]; bool vin[8];
    float lm = -3.4e38f;
    #pragma unroll
    for (int t = 0; t < 8; t++) {
        int p = lane + 32 * t;
        vin[t] = p < cnt;
        cv[t] = vin[t] ? bv[p] : -3.4e38f;
        ci[t] = vin[t] ? bi[p] : 0;
        lm = fmaxf(lm, cv[t]);
    }
    lm = k2f(__reduce_min_sync(0xffffffffu, f2k(lm)));
    __syncwarp();

    int base = 0;
    #pragma unroll
    for (int t = 0; t < 8; t++) {
        bool keep = vin[t] && (cv[t] >= lm);
        unsigned bal = __ballot_sync(0xffffffffu, keep);
        if (keep) {
            int pos = base + __popc(bal & ((1u << lane) - 1u));
            bv[pos] = cv[t]; bi[pos] = ci[t];
        }
        base += __popc(bal);
    }
    __syncwarp();
    thr = lm;
    return base;
}

// ---------------- top-20 per row: 8-wide streaming filter -------------------
// Two float4 per iteration share ONE quick-reject ballot. Compaction check
// after each 4-group keeps cnt <= 128 + 128 <= TQCAP.
__global__ __launch_bounds__(256) void topk_kernel() {
    int tid = threadIdx.x, lane = tid & 31, w = tid >> 5;
    int row = blockIdx.x * 8 + w;
    const float4* r4 = (const float4*)(g_D + (size_t)row * NPT);

    __shared__ float sbv[8][TQCAP];
    __shared__ int   sbi[8][TQCAP];
    float* bv = sbv[w]; int* bi = sbi[w];

    float thr; int thri = 0x7fffffff;
    int cnt;

    // tiles 0-1: everything passes — positional append, zero ballots
    {
        float4 d0 = r4[lane], d1 = r4[lane + 32];
        int p0 = lane * 4, p1 = 128 + lane * 4;
        bv[p0] = d0.x; bv[p0 + 1] = d0.y; bv[p0 + 2] = d0.z; bv[p0 + 3] = d0.w;
        bi[p0] = lane * 4;     bi[p0 + 1] = lane * 4 + 1;
        bi[p0 + 2] = lane * 4 + 2; bi[p0 + 3] = lane * 4 + 3;
        int b1 = (lane + 32) * 4;
        bv[p1] = d1.x; bv[p1 + 1] = d1.y; bv[p1 + 2] = d1.z; bv[p1 + 3] = d1.w;
        bi[p1] = b1; bi[p1 + 1] = b1 + 1; bi[p1 + 2] = b1 + 2; bi[p1 + 3] = b1 + 3;
        __syncwarp();
        cnt = cheap_compact(bv, bi, 256, lane, thr);
        if (cnt > 128) { warp_select20(bv, bi, cnt, lane, thr); cnt = KNN; }
    }

    float4 p0 = r4[lane + 64], p1 = r4[lane + 96];
    #pragma unroll 1
    for (int t = 2; t < 32; t += 2) {
        float4 d0 = p0, d1 = p1;
        if (t + 2 < 32) { p0 = r4[lane + 32 * (t + 2)]; p1 = r4[lane + 32 * (t + 3)]; }
        float m = fmaxf(fmaxf(fmaxf(d0.x, d0.y), fmaxf(d0.z, d0.w)),
                        fmaxf(fmaxf(d1.x, d1.y), fmaxf(d1.z, d1.w)));
        if (__ballot_sync(0xffffffffu, m >= thr)) {
            // group 0 (chunk t)
            {
                int base = (lane + 32 * t) << 2;
                float dv[4] = {d0.x, d0.y, d0.z, d0.w};
                #pragma unroll
                for (int c = 0; c < 4; c++) {
                    bool pass = better(dv[c], base + c, thr, thri);
                    unsigned bal = __ballot_sync(0xffffffffu, pass);
                    if (pass) {
                        int pos = cnt + __popc(bal & ((1u << lane) - 1u));
                        bv[pos] = dv[c]; bi[pos] = base + c;
                    }
                    cnt += __popc(bal);
                }
                if (cnt > 128) {
                    cnt = cheap_compact(bv, bi, cnt, lane, thr);
                    if (cnt > 128) { warp_select20(bv, bi, cnt, lane, thr); cnt = KNN; }
                }
            }
            // group 1 (chunk t+1)
            {
                int base = (lane + 32 * (t + 1)) << 2;
                float dv[4] = {d1.x, d1.y, d1.z, d1.w};
                #pragma unroll
                for (int c = 0; c < 4; c++) {
                    bool pass = better(dv[c], base + c, thr, thri);
                    unsigned bal = __ballot_sync(0xffffffffu, pass);
                    if (pass) {
                        int pos = cnt + __popc(bal & ((1u << lane) - 1u));
                        bv[pos] = dv[c]; bi[pos] = base + c;
                    }
                    cnt += __popc(bal);
                }
                if (cnt > 128) {
                    cnt = cheap_compact(bv, bi, cnt, lane, thr);
                    if (cnt > 128) { warp_select20(bv, bi, cnt, lane, thr); cnt = KNN; }
                }
            }
        }
    }
    __syncwarp();
    if (cnt > KNN) warp_select20(bv, bi, cnt, lane, thr);
    if (lane < KNN) g_idx[row * KNN + lane] = bi[lane];
}

// ---------------- fused P/Q GEMM with folded BatchNorm -----------------------
__global__ __launch_bounds__(256) void pq_gemm(
    const float* __restrict__ feat, const float* __restrict__ W,
    const float* __restrict__ gg, const float* __restrict__ bb,
    const float* __restrict__ mm, const float* __restrict__ vv,
    int C, int O)
{
    const float* f = feat ? feat : g_feat;
    int i0 = blockIdx.y * 64;
    int o0 = blockIdx.x * 64;

    __shared__ __align__(16) float As[16][68];
    __shared__ __align__(16) float B1[16][68];
    __shared__ __align__(16) float B2[16][68];

    int tid = threadIdx.x;
    int tx = tid & 15, ty = tid >> 4;
    int lc = tid & 15, lr0 = tid >> 4;
    int twoC = 2 * C;

    float acc1[4][4], acc2[4][4];
    #pragma unroll
    for (int i = 0; i < 4; i++)
        #pragma unroll
        for (int j = 0; j < 4; j++) { acc1[i][j] = 0.f; acc2[i][j] = 0.f; }

    for (int k0 = 0; k0 < C; k0 += 16) {
        bool kin = (k0 + lc) < C;
        #pragma unroll
        for (int q = 0; q < 4; q++) {
            int r = lr0 + q * 16;
            As[lc][r] = kin ? f[(size_t)(i0 + r) * C + k0 + lc] : 0.f;
            B1[lc][r] = kin ? W[(size_t)(o0 + r) * twoC + k0 + lc] : 0.f;
            B2[lc][r] = kin ? W[(size_t)(o0 + r) * twoC + C + k0 + lc] : 0.f;
        }
        __syncthreads();
        #pragma unroll
        for (int kk = 0; kk < 16; kk++) {
            float4 a4  = *(const float4*)&As[kk][ty * 4];
            float4 b14 = *(const float4*)&B1[kk][tx * 4];
            float4 b24 = *(const float4*)&B2[kk][tx * 4];
            float av[4]  = {a4.x, a4.y, a4.z, a4.w};
            float b1v[4] = {b14.x, b14.y, b14.z, b14.w};
            float b2v[4] = {b24.x, b24.y, b24.z, b24.w};
            #pragma unroll
            for (int i = 0; i < 4; i++)
                #pragma unroll
                for (int j = 0; j < 4; j++) {
                    acc1[i][j] += av[i] * b1v[j];
                    acc2[i][j] += av[i] * b2v[j];
                }
        }
        __syncthreads();
    }

    #pragma unroll
    for (int j = 0; j < 4; j++) {
        int o = o0 + tx * 4 + j;
        float s = gg[o] * rsqrtf(vv[o] + BNEPS);
        float t = bb[o] - s * mm[o];
        #pragma unroll
        for (int i = 0; i < 4; i++) {
            int gi = i0 + ty * 4 + i;
            g_Pp[(size_t)gi * O + o] = s * acc1[i][j];
            g_Qq[(size_t)gi * O + o] = s * (acc2[i][j] - acc1[i][j]) + t;
        }
    }
}

// ---------------- gather neighbors + max + leaky relu ------------------------
__global__ __launch_bounds__(128) void gmax_kernel(int O, float* __restrict__ outp) {
    float* out = outp ? outp : g_feat;
    int bn = blockIdx.x;
    int b  = bn / NPT;
    __shared__ int sidx[KNN];
    if (threadIdx.x < KNN) sidx[threadIdx.x] = g_idx[bn * KNN + threadIdx.x];
    __syncthreads();
    size_t base = (size_t)b * NPT;
    for (int o = threadIdx.x; o < O; o += blockDim.x) {
        float q = g_Qq[(size_t)bn * O + o];
        float m = -3.4e38f;
        #pragma unroll
        for (int k = 0; k < KNN; k++) {
            float v = g_Pp[(base + sidx[k]) * O + o] + q;
            m = fmaxf(m, v);
        }
        out[(size_t)bn * O + o] = (m >= 0.f) ? m : NEG * m;
    }
}

// ---------------- host orchestration -----------------------------------------
// Round-14 structure (single dist launch, serialized dist->topk) + ONE small
// fork: pq_gemm runs on a side stream (it needs only the layer input and is
// consumed only by gmax), hiding its ~11us under dist. Join before gmax.
extern "C" void kernel_launch(void* const* d_in, const int* in_sizes, int n_in,
                              void* d_out, int out_size)
{
    (void)in_sizes; (void)n_in; (void)out_size;
    const float* x = (const float*)d_in[0];
    static const int dims[5] = {3, 64, 64, 128, 256};

    cudaStream_t s1;
    cudaStreamCreateWithFlags(&s1, cudaStreamNonBlocking);

    const float* fin = x;
    for (int l = 0; l < 4; l++) {
        int C = dims[l], O = dims[l + 1];
        const float* Wl = (const float*)d_in[1 + l * 5];
        const float* gl = (const float*)d_in[2 + l * 5];
        const float* bl = (const float*)d_in[3 + l * 5];
        const float* ml = (const float*)d_in[4 + l * 5];
        const float* vl = (const float*)d_in[5 + l * 5];

        // fork: pq depends only on fin (= previous gmax output, ordered on
        // stream 0); event also orders pq's Pp/Qq writes after the previous
        // layer's gmax reads.
        cudaEvent_t eF;
        cudaEventCreateWithFlags(&eF, cudaEventDisableTiming);
        cudaEventRecord(eF, 0);
        cudaStreamWaitEvent(s1, eF, 0);
        pq_gemm<<<dim3(O / 64, (BATCH * NPT) / 64), 256, 0, s1>>>(fin, Wl, gl, bl, ml, vl, C, O);
        cudaEvent_t eP;
        cudaEventCreateWithFlags(&eP, cudaEventDisableTiming);
        cudaEventRecord(eP, s1);

        sqnorm_kernel<<<(BATCH * NPT) / 16, 256>>>(fin, C, 0);
        sqnorm_kernel<<<(BATCH * NPT) / 16, 256>>>(fin, C, (BATCH * NPT) / 2);
        dist_gemm<<<dim3(NTRI, 1, BATCH), 256>>>(fin, C);
        topk_kernel<<<(BATCH * NPT) / 8, 256>>>();

        // join: gmax needs pq results
        cudaStreamWaitEvent(0, eP, 0);
        gmax_kernel<<<BATCH * NPT, 128>>>(O, (l == 3) ? (float*)d_out : nullptr);

        fin = nullptr;
    }
}